// round 2
// baseline (speedup 1.0000x reference)
#include <cuda_runtime.h>

// ---------------- problem constants ----------------
#define LL 8
#define HH 256
#define WW 448
#define KL 2
#define KH 18
#define KW 32
#define KK (KL*KH*KW)        // 1152 superpixels
#define HW (HH*WW)           // 114688
#define NN (LL*HW)           // 917504 pixels
#define RUNW 14              // W / KW = exact pixels per kw cell
#define NRUNS (NN/RUNW)      // 65536 runs (one warp each)

#define T_SCALE   0.625f                 // Kl/(0.4*L)
#define YX_SCALE  0.17857142857142858f   // max(Kh/(0.4*H), Kw/(0.4*W)) = 32/179.2
#define LAB_SCALE 0.26f

#define FULLMASK 0xFFFFFFFFu

// ---------------- persistent scratch (no allocs allowed) ----------------
__device__ float g_spFeat[KK * 6];   // cluster features
__device__ float g_acc[KK * 8];      // [0..5]=sum a*f, [6]=sum a (or count), [7]=pad

// ---------------- kernels ----------------
__global__ void zero_acc_kernel() {
    int i = blockIdx.x * blockDim.x + threadIdx.x;
    if (i < KK * 8) g_acc[i] = 0.0f;
}

// Writes pFeat5 output and accumulates the scatter-mean init (per-run warp reduce).
__global__ void init_kernel(const float* __restrict__ lab,
                            float* __restrict__ outPFeat) {
    int gw   = (blockIdx.x * blockDim.x + threadIdx.x) >> 5;
    int lane = threadIdx.x & 31;
    int rx  = gw & (KW - 1);
    int row = gw >> 5;
    int y = row & (HH - 1);
    int t = row >> 8;
    int x0 = rx * RUNW;
    int kl = t >> 2;
    int kh = (y * KH) >> 8;
    int c0 = kl * (KH * KW) + kh * KW + rx;

    float f0 = 0.f, f1 = 0.f, f2 = 0.f, f3 = 0.f, f4 = 0.f, f5 = 0.f;
    if (lane < RUNW) {
        int x = x0 + lane;
        int pix = t * HW + y * WW + x;
        f0 = T_SCALE * (float)t;
        f1 = YX_SCALE * (float)y;
        f2 = YX_SCALE * (float)x;
        f3 = LAB_SCALE * __ldg(lab + pix);
        f4 = LAB_SCALE * __ldg(lab + NN + pix);
        f5 = LAB_SCALE * __ldg(lab + 2 * NN + pix);
        outPFeat[pix]          = f0;
        outPFeat[NN + pix]     = f1;
        outPFeat[2 * NN + pix] = f2;
        outPFeat[3 * NN + pix] = f3;
        outPFeat[4 * NN + pix] = f4;
        outPFeat[5 * NN + pix] = f5;
    }
    // warp reduce 6 sums
    float s0 = f0, s1 = f1, s2 = f2, s3 = f3, s4 = f4, s5 = f5;
    #pragma unroll
    for (int o = 16; o; o >>= 1) {
        s0 += __shfl_xor_sync(FULLMASK, s0, o);
        s1 += __shfl_xor_sync(FULLMASK, s1, o);
        s2 += __shfl_xor_sync(FULLMASK, s2, o);
        s3 += __shfl_xor_sync(FULLMASK, s3, o);
        s4 += __shfl_xor_sync(FULLMASK, s4, o);
        s5 += __shfl_xor_sync(FULLMASK, s5, o);
    }
    if (lane == 0) {
        float* g = g_acc + c0 * 8;
        atomicAdd(g + 0, s0); atomicAdd(g + 1, s1); atomicAdd(g + 2, s2);
        atomicAdd(g + 3, s3); atomicAdd(g + 4, s4); atomicAdd(g + 5, s5);
        atomicAdd(g + 6, (float)RUNW);
    }
}

// MODE 0: init normalize (divide by max(count,1)); MODE 1: EM update (max(w,1e-12)).
// Also zeros the accumulator for the next pass, and optionally emits spFeat^T output.
template <int MODE>
__global__ void norm_kernel(float* __restrict__ spOut) {
    int k = blockIdx.x * blockDim.x + threadIdx.x;
    if (k >= KK) return;
    float w = g_acc[k * 8 + 6];
    float denom = (MODE == 0) ? fmaxf(w, 1.0f) : fmaxf(w, 1e-12f);
    #pragma unroll
    for (int c = 0; c < 6; c++) {
        float v = g_acc[k * 8 + c] / denom;
        g_spFeat[k * 6 + c] = v;
        g_acc[k * 8 + c] = 0.0f;
        if (spOut) spOut[c * KK + k] = v;
    }
    g_acc[k * 8 + 6] = 0.0f;
}

// One EM pass. Warp = one 14-pixel run; lane j<27 = neighbor j.
// FINAL=false: accumulate weighted scatter into g_acc.
// FINAL=true : write psp_assoc + argmax -> final index.
template <bool FINAL>
__global__ void em_kernel(const float* __restrict__ lab,
                          float* __restrict__ outAssoc,
                          float* __restrict__ outFinal) {
    int gw = (blockIdx.x * blockDim.x + threadIdx.x) >> 5;
    int j  = threadIdx.x & 31;
    int rx  = gw & (KW - 1);
    int row = gw >> 5;
    int y = row & (HH - 1);
    int t = row >> 8;
    int x0 = rx * RUNW;
    int kl = t >> 2;
    int kh = (y * KH) >> 8;

    bool act = (j < 27);
    int dl = j / 9 - 1;
    int dh = (j % 9) / 3 - 1;
    int dw = j % 3 - 1;
    int nl = kl + dl, nh = kh + dh, nw = rx + dw;
    bool valid = act && (nl >= 0) && (nl < KL) && (nh >= 0) && (nh < KH)
                     && (nw >= 0) && (nw < KW);
    int nlc = min(max(nl, 0), KL - 1);
    int nhc = min(max(nh, 0), KH - 1);
    int nwc = min(max(nw, 0), KW - 1);
    int nidx = nlc * (KH * KW) + nhc * KW + nwc;

    float s0 = 0.f, s1 = 0.f, s2 = 0.f, s3 = 0.f, s4 = 0.f, s5 = 0.f;
    if (act) {
        const float* sp = g_spFeat + nidx * 6;
        s0 = __ldg(sp + 0); s1 = __ldg(sp + 1); s2 = __ldg(sp + 2);
        s3 = __ldg(sp + 3); s4 = __ldg(sp + 4); s5 = __ldg(sp + 5);
    }

    float fT = T_SCALE * (float)t;
    float fY = YX_SCALE * (float)y;
    int base = t * HW + y * WW + x0;

    float aw = 0.f, a0 = 0.f, a1 = 0.f, a2 = 0.f, a3 = 0.f, a4 = 0.f, a5 = 0.f;

    #pragma unroll
    for (int p = 0; p < RUNW; p++) {
        float fX = YX_SCALE * (float)(x0 + p);
        float l0 = LAB_SCALE * __ldg(lab + base + p);
        float l1 = LAB_SCALE * __ldg(lab + NN + base + p);
        float l2 = LAB_SCALE * __ldg(lab + 2 * NN + base + p);

        float t0 = fT - s0, t1 = fY - s1, t2 = fX - s2;
        float t3 = l0 - s3, t4 = l1 - s4, t5 = l2 - s5;
        float d = t0 * t0 + t1 * t1 + t2 * t2 + t3 * t3 + t4 * t4 + t5 * t5;

        // softmax over 27 neighbors: d >= 0 and d_min is small (pixel inside
        // its own cell), so exp(-d) needs no max-subtraction.
        float e = valid ? __expf(-d) : 0.0f;
        float sum = e;
        #pragma unroll
        for (int o = 16; o; o >>= 1) sum += __shfl_xor_sync(FULLMASK, sum, o);
        float a = e / sum;

        if (FINAL) {
            if (act) outAssoc[j * NN + base + p] = a;
            // warp argmax, first-index tiebreak (numpy semantics)
            float bv = a;
            int bj = act ? j : 64;
            #pragma unroll
            for (int o = 16; o; o >>= 1) {
                float ov = __shfl_xor_sync(FULLMASK, bv, o);
                int   oj = __shfl_xor_sync(FULLMASK, bj, o);
                if (ov > bv || (ov == bv && oj < bj)) { bv = ov; bj = oj; }
            }
            int nbest = __shfl_sync(FULLMASK, nidx, bj);
            if (j == 0) outFinal[base + p] = (float)nbest;
        } else {
            aw += a;
            a0 = fmaf(a, fT, a0);
            a1 = fmaf(a, fY, a1);
            a2 = fmaf(a, fX, a2);
            a3 = fmaf(a, l0, a3);
            a4 = fmaf(a, l1, a4);
            a5 = fmaf(a, l2, a5);
        }
    }

    if (!FINAL && valid) {
        float* g = g_acc + nidx * 8;
        atomicAdd(g + 0, a0); atomicAdd(g + 1, a1); atomicAdd(g + 2, a2);
        atomicAdd(g + 3, a3); atomicAdd(g + 4, a4); atomicAdd(g + 5, a5);
        atomicAdd(g + 6, aw);
    }
}

// ---------------- launch ----------------
extern "C" void kernel_launch(void* const* d_in, const int* in_sizes, int n_in,
                              void* d_out, int out_size) {
    const float* lab = (const float*)d_in[0];   // vid_lab (1,3,L,H,W)
    // d_in[1] = init_spIndx (regular grid; recomputed analytically in-kernel)

    float* out = (float*)d_out;
    float* outPFeat = out;                               // 6*N
    float* outSp    = out + 6 * NN;                      // 6*K
    float* outAssoc = out + 6 * NN + 6 * KK;             // 27*N
    float* outFinal = out + 6 * NN + 6 * KK + 27 * NN;   // N

    const int EM_BLOCKS = NRUNS / 8;   // 8 warps (runs) per 256-thread block

    zero_acc_kernel<<<(KK * 8 + 255) / 256, 256>>>();
    init_kernel<<<EM_BLOCKS, 256>>>(lab, outPFeat);
    norm_kernel<0><<<(KK + 127) / 128, 128>>>(nullptr);

    for (int it = 0; it < 4; it++) {
        em_kernel<false><<<EM_BLOCKS, 256>>>(lab, nullptr, nullptr);
        norm_kernel<1><<<(KK + 127) / 128, 128>>>(it == 3 ? outSp : nullptr);
    }
    em_kernel<true><<<EM_BLOCKS, 256>>>(lab, outAssoc, outFinal);
}

// round 3
// speedup vs baseline: 1.2921x; 1.2921x over previous
#include <cuda_runtime.h>

// ---------------- problem constants ----------------
#define LL 8
#define HH 256
#define WW 448
#define KL 2
#define KH 18
#define KW 32
#define KK (KL*KH*KW)        // 1152 superpixels
#define HW (HH*WW)           // 114688
#define NN (LL*HW)           // 917504 pixels
#define RUNW 14              // W / KW = exact pixels per kw cell
#define NRUNS (NN/RUNW)      // 65536 runs (one warp each)

#define T_SCALE   0.625f                 // Kl/(0.4*L)
#define YX_SCALE  0.17857142857142858f   // max(Kh/(0.4*H), Kw/(0.4*W))
#define LAB_SCALE 0.26f

#define FULLMASK 0xFFFFFFFFu

// ---------------- persistent scratch (no allocs allowed) ----------------
__device__ float g_spFeat[KK * 6];   // cluster features
__device__ float g_acc[KK * 8];      // [0..5]=sum a*f, [6]=sum a, [7]=pad

// ---------------- kernels ----------------
__global__ void zero_acc_kernel() {
    int i = blockIdx.x * blockDim.x + threadIdx.x;
    if (i < KK * 8) g_acc[i] = 0.0f;
}

// Writes pFeat5 output and accumulates the scatter-mean init (per-run warp reduce).
__global__ void init_kernel(const float* __restrict__ lab,
                            float* __restrict__ outPFeat) {
    int gw   = (blockIdx.x * blockDim.x + threadIdx.x) >> 5;
    int lane = threadIdx.x & 31;
    int rx  = gw & (KW - 1);
    int row = gw >> 5;
    int y = row & (HH - 1);
    int t = row >> 8;
    int x0 = rx * RUNW;
    int kl = t >> 2;
    int kh = (y * KH) >> 8;
    int c0 = kl * (KH * KW) + kh * KW + rx;

    float f0 = 0.f, f1 = 0.f, f2 = 0.f, f3 = 0.f, f4 = 0.f, f5 = 0.f;
    if (lane < RUNW) {
        int x = x0 + lane;
        int pix = t * HW + y * WW + x;
        f0 = T_SCALE * (float)t;
        f1 = YX_SCALE * (float)y;
        f2 = YX_SCALE * (float)x;
        f3 = LAB_SCALE * __ldg(lab + pix);
        f4 = LAB_SCALE * __ldg(lab + NN + pix);
        f5 = LAB_SCALE * __ldg(lab + 2 * NN + pix);
        outPFeat[pix]          = f0;
        outPFeat[NN + pix]     = f1;
        outPFeat[2 * NN + pix] = f2;
        outPFeat[3 * NN + pix] = f3;
        outPFeat[4 * NN + pix] = f4;
        outPFeat[5 * NN + pix] = f5;
    }
    float s0 = f0, s1 = f1, s2 = f2, s3 = f3, s4 = f4, s5 = f5;
    #pragma unroll
    for (int o = 16; o; o >>= 1) {
        s0 += __shfl_xor_sync(FULLMASK, s0, o);
        s1 += __shfl_xor_sync(FULLMASK, s1, o);
        s2 += __shfl_xor_sync(FULLMASK, s2, o);
        s3 += __shfl_xor_sync(FULLMASK, s3, o);
        s4 += __shfl_xor_sync(FULLMASK, s4, o);
        s5 += __shfl_xor_sync(FULLMASK, s5, o);
    }
    if (lane == 0) {
        float* g = g_acc + c0 * 8;
        atomicAdd(g + 0, s0); atomicAdd(g + 1, s1); atomicAdd(g + 2, s2);
        atomicAdd(g + 3, s3); atomicAdd(g + 4, s4); atomicAdd(g + 5, s5);
        atomicAdd(g + 6, (float)RUNW);
    }
}

// MODE 0: init normalize; MODE 1: EM update. Zeros acc for the next pass.
template <int MODE>
__global__ void norm_kernel(float* __restrict__ spOut) {
    int k = blockIdx.x * blockDim.x + threadIdx.x;
    if (k >= KK) return;
    float w = g_acc[k * 8 + 6];
    float denom = (MODE == 0) ? fmaxf(w, 1.0f) : fmaxf(w, 1e-12f);
    #pragma unroll
    for (int c = 0; c < 6; c++) {
        float v = g_acc[k * 8 + c] / denom;
        g_spFeat[k * 6 + c] = v;
        g_acc[k * 8 + c] = 0.0f;
        if (spOut) spOut[c * KK + k] = v;
    }
    g_acc[k * 8 + 6] = 0.0f;
}

// One EM pass. Warp = one 14-pixel run; lane j<27 = neighbor j.
// Phased: (A) all 14 exp(-d) -> e[]  (B) 14 independent butterflies -> sums
// (C) normalize + accumulate / emit.
template <bool FINAL>
__global__ void __launch_bounds__(256)
em_kernel(const float* __restrict__ lab,
          float* __restrict__ outAssoc,
          float* __restrict__ outFinal) {
    __shared__ float sA[FINAL ? 27 : 1][FINAL ? 113 : 1];
    __shared__ float sF[FINAL ? 112 : 1];

    int w  = threadIdx.x >> 5;
    int j  = threadIdx.x & 31;
    int gw = blockIdx.x * 8 + w;
    int rx  = gw & (KW - 1);
    int row = gw >> 5;
    int y = row & (HH - 1);
    int t = row >> 8;
    int x0 = rx * RUNW;
    int kl = t >> 2;
    int kh = (y * KH) >> 8;

    bool act = (j < 27);
    int dl = j / 9 - 1;
    int dh = (j % 9) / 3 - 1;
    int dw = j % 3 - 1;
    int nl = kl + dl, nh = kh + dh, nw = rx + dw;
    bool valid = act && (nl >= 0) && (nl < KL) && (nh >= 0) && (nh < KH)
                     && (nw >= 0) && (nw < KW);
    int nlc = min(max(nl, 0), KL - 1);
    int nhc = min(max(nh, 0), KH - 1);
    int nwc = min(max(nw, 0), KW - 1);
    int nidx = nlc * (KH * KW) + nhc * KW + nwc;

    float s0 = 0.f, s1 = 0.f, s2 = 0.f, s3 = 0.f, s4 = 0.f, s5 = 0.f;
    if (act) {
        const float* sp = g_spFeat + nidx * 6;
        s0 = __ldg(sp + 0); s1 = __ldg(sp + 1); s2 = __ldg(sp + 2);
        s3 = __ldg(sp + 3); s4 = __ldg(sp + 4); s5 = __ldg(sp + 5);
    }

    float fT = T_SCALE * (float)t;
    float fY = YX_SCALE * (float)y;
    float fX0 = YX_SCALE * (float)x0;
    int base = t * HW + y * WW + x0;

    // per-lane constants of the distance
    float tT = fT - s0, tY = fY - s1;
    float dYT = tT * tT + tY * tY;
    float tX0 = fX0 - s2;

    const float* lb0 = lab + base;
    const float* lb1 = lab + NN + base;
    const float* lb2 = lab + 2 * NN + base;

    // ---- phase A: e[p] = valid ? exp(-d_p) : 0 ----
    float e[RUNW], sm[RUNW];
    #pragma unroll
    for (int p = 0; p < RUNW; p++) {
        float tX = fmaf((float)p, YX_SCALE, tX0);
        float l0 = fmaf(LAB_SCALE, __ldg(lb0 + p), -s3);
        float l1 = fmaf(LAB_SCALE, __ldg(lb1 + p), -s4);
        float l2 = fmaf(LAB_SCALE, __ldg(lb2 + p), -s5);
        float d = fmaf(tX, tX, dYT);
        d = fmaf(l0, l0, d);
        d = fmaf(l1, l1, d);
        d = fmaf(l2, l2, d);
        e[p] = valid ? __expf(-d) : 0.0f;
        sm[p] = e[p];
    }

    // ---- phase B: 14 independent 32-lane sum butterflies ----
    #pragma unroll
    for (int o = 16; o; o >>= 1) {
        #pragma unroll
        for (int p = 0; p < RUNW; p++)
            sm[p] += __shfl_xor_sync(FULLMASK, sm[p], o);
    }

    // ---- phase C ----
    if (!FINAL) {
        float aw = 0.f, ap = 0.f, a3 = 0.f, a4 = 0.f, a5 = 0.f;
        #pragma unroll
        for (int p = 0; p < RUNW; p++) {
            float a = __fdividef(e[p], sm[p]);
            aw += a;
            ap = fmaf(a, (float)p, ap);
            a3 = fmaf(a, __ldg(lb0 + p), a3);
            a4 = fmaf(a, __ldg(lb1 + p), a4);
            a5 = fmaf(a, __ldg(lb2 + p), a5);
        }
        if (valid) {
            float* g = g_acc + nidx * 8;
            atomicAdd(g + 0, fT * aw);
            atomicAdd(g + 1, fY * aw);
            atomicAdd(g + 2, fmaf(YX_SCALE, ap, fX0 * aw));
            atomicAdd(g + 3, LAB_SCALE * a3);
            atomicAdd(g + 4, LAB_SCALE * a4);
            atomicAdd(g + 5, LAB_SCALE * a5);
            atomicAdd(g + 6, aw);
        }
    } else {
        #pragma unroll
        for (int p = 0; p < RUNW; p++) {
            float a = __fdividef(e[p], sm[p]);
            if (act) sA[j][w * RUNW + p] = a;
            // exact argmax, first-index tiebreak: a>=0 so float order == uint order
            unsigned b  = valid ? __float_as_uint(a) : 0u;
            unsigned mb = __reduce_max_sync(FULLMASK, b);
            unsigned ball = __ballot_sync(FULLMASK, valid && (b == mb));
            int j0 = __ffs(ball) - 1;
            int nbest = __shfl_sync(FULLMASK, nidx, j0);
            if (j == 0) sF[w * RUNW + p] = (float)nbest;
        }
        __syncthreads();
        // block covers 112 consecutive x pixels of one (t,y) row
        int rx0   = (blockIdx.x & 3) * 8;          // first rx of block
        int xbase = t * HW + y * WW + rx0 * RUNW;  // t,y same for all warps in block
        #pragma unroll 4
        for (int i = threadIdx.x; i < 27 * 112; i += 256) {
            int jj = i / 112;
            int c  = i - jj * 112;
            outAssoc[jj * NN + xbase + c] = sA[jj][c];
        }
        if (threadIdx.x < 112)
            outFinal[xbase + threadIdx.x] = sF[threadIdx.x];
    }
}

// ---------------- launch ----------------
extern "C" void kernel_launch(void* const* d_in, const int* in_sizes, int n_in,
                              void* d_out, int out_size) {
    const float* lab = (const float*)d_in[0];   // vid_lab (1,3,L,H,W)
    // d_in[1] = init_spIndx (regular grid; recomputed analytically in-kernel)

    float* out = (float*)d_out;
    float* outPFeat = out;                               // 6*N
    float* outSp    = out + 6 * NN;                      // 6*K
    float* outAssoc = out + 6 * NN + 6 * KK;             // 27*N
    float* outFinal = out + 6 * NN + 6 * KK + 27 * NN;   // N

    const int EM_BLOCKS = NRUNS / 8;   // 8 warps (runs) per 256-thread block

    zero_acc_kernel<<<(KK * 8 + 255) / 256, 256>>>();
    init_kernel<<<EM_BLOCKS, 256>>>(lab, outPFeat);
    norm_kernel<0><<<(KK + 127) / 128, 128>>>(nullptr);

    for (int it = 0; it < 4; it++) {
        em_kernel<false><<<EM_BLOCKS, 256>>>(lab, nullptr, nullptr);
        norm_kernel<1><<<(KK + 127) / 128, 128>>>(it == 3 ? outSp : nullptr);
    }
    em_kernel<true><<<EM_BLOCKS, 256>>>(lab, outAssoc, outFinal);
}

// round 4
// speedup vs baseline: 2.8633x; 2.2159x over previous
#include <cuda_runtime.h>

// ---------------- problem constants ----------------
#define LL 8
#define HH 256
#define WW 448
#define KL 2
#define KH 18
#define KW 32
#define KK (KL*KH*KW)        // 1152 superpixels
#define HW (HH*WW)           // 114688
#define NN (LL*HW)           // 917504 pixels
#define RUNW 14              // W / KW = exact pixels per kw cell
#define NRUNS (NN/RUNW)      // 65536 runs (one warp each)
#define RREP 4               // accumulator replicas (contention relief)

#define T_SCALE   0.625f                 // Kl/(0.4*L)
#define YX_SCALE  0.17857142857142858f   // max(Kh/(0.4*H), Kw/(0.4*W))
#define LAB_SCALE 0.26f

#define FXSCALE   33554432.0f            // 2^25 fixed-point softmax denominator
#define FXINV     (1.0f/33554432.0f)

#define FULLMASK 0xFFFFFFFFu

// ---------------- persistent scratch (no allocs allowed) ----------------
__device__ float g_spFeat[KK * 6];                       // cluster features
__device__ __align__(32) float g_acc[RREP][KK][8];       // [0..5]=sum a*f, [6]=sum a, [7]=pad

// ---------------- kernels ----------------
__global__ void zero_acc_kernel() {
    int i = blockIdx.x * blockDim.x + threadIdx.x;
    if (i < RREP * KK * 8) ((float*)g_acc)[i] = 0.0f;
}

// Writes pFeat5 output and accumulates the scatter-mean init (per-run warp reduce).
__global__ void init_kernel(const float* __restrict__ lab,
                            float* __restrict__ outPFeat) {
    int gw   = (blockIdx.x * blockDim.x + threadIdx.x) >> 5;
    int lane = threadIdx.x & 31;
    int rx  = gw & (KW - 1);
    int row = gw >> 5;
    int y = row & (HH - 1);
    int t = row >> 8;
    int x0 = rx * RUNW;
    int kl = t >> 2;
    int kh = (y * KH) >> 8;
    int c0 = kl * (KH * KW) + kh * KW + rx;

    float f0 = 0.f, f1 = 0.f, f2 = 0.f, f3 = 0.f, f4 = 0.f, f5 = 0.f;
    if (lane < RUNW) {
        int x = x0 + lane;
        int pix = t * HW + y * WW + x;
        f0 = T_SCALE * (float)t;
        f1 = YX_SCALE * (float)y;
        f2 = YX_SCALE * (float)x;
        f3 = LAB_SCALE * __ldg(lab + pix);
        f4 = LAB_SCALE * __ldg(lab + NN + pix);
        f5 = LAB_SCALE * __ldg(lab + 2 * NN + pix);
        outPFeat[pix]          = f0;
        outPFeat[NN + pix]     = f1;
        outPFeat[2 * NN + pix] = f2;
        outPFeat[3 * NN + pix] = f3;
        outPFeat[4 * NN + pix] = f4;
        outPFeat[5 * NN + pix] = f5;
    }
    float s0 = f0, s1 = f1, s2 = f2, s3 = f3, s4 = f4, s5 = f5;
    #pragma unroll
    for (int o = 16; o; o >>= 1) {
        s0 += __shfl_xor_sync(FULLMASK, s0, o);
        s1 += __shfl_xor_sync(FULLMASK, s1, o);
        s2 += __shfl_xor_sync(FULLMASK, s2, o);
        s3 += __shfl_xor_sync(FULLMASK, s3, o);
        s4 += __shfl_xor_sync(FULLMASK, s4, o);
        s5 += __shfl_xor_sync(FULLMASK, s5, o);
    }
    if (lane == 0) {
        int rep = blockIdx.x & (RREP - 1);
        atomicAdd((float4*)&g_acc[rep][c0][0], make_float4(s0, s1, s2, s3));
        atomicAdd((float4*)&g_acc[rep][c0][4], make_float4(s4, s5, (float)RUNW, 0.f));
    }
}

// MODE 0: init normalize; MODE 1: EM update. Folds RREP replicas, zeros them.
template <int MODE>
__global__ void norm_kernel(float* __restrict__ spOut) {
    int k = blockIdx.x * blockDim.x + threadIdx.x;
    if (k >= KK) return;
    float acc[7];
    #pragma unroll
    for (int c = 0; c < 7; c++) acc[c] = 0.0f;
    #pragma unroll
    for (int r = 0; r < RREP; r++) {
        #pragma unroll
        for (int c = 0; c < 7; c++) {
            acc[c] += g_acc[r][k][c];
            g_acc[r][k][c] = 0.0f;
        }
    }
    float w = acc[6];
    float denom = (MODE == 0) ? fmaxf(w, 1.0f) : fmaxf(w, 1e-12f);
    float inv = 1.0f / denom;
    #pragma unroll
    for (int c = 0; c < 6; c++) {
        float v = acc[c] * inv;
        g_spFeat[k * 6 + c] = v;
        if (spOut) spOut[c * KK + k] = v;
    }
}

// One EM pass. Warp = one 14-pixel run; lane j<27 = neighbor j.
// Softmax reduction: REDUX min(d) -> exp(dmin-d) in (0,1] -> fixed-point REDUX add.
template <bool FINAL>
__global__ void __launch_bounds__(256)
em_kernel(const float* __restrict__ lab,
          float* __restrict__ outAssoc,
          float* __restrict__ outFinal) {
    __shared__ float sA[FINAL ? 27 : 1][FINAL ? 113 : 1];
    __shared__ float sF[FINAL ? 112 : 1];

    int w  = threadIdx.x >> 5;
    int j  = threadIdx.x & 31;
    int gw = blockIdx.x * 8 + w;
    int rx  = gw & (KW - 1);
    int row = gw >> 5;
    int y = row & (HH - 1);
    int t = row >> 8;
    int x0 = rx * RUNW;
    int kl = t >> 2;
    int kh = (y * KH) >> 8;

    bool act = (j < 27);
    int dl = j / 9 - 1;
    int dh = (j % 9) / 3 - 1;
    int dw = j % 3 - 1;
    int nl = kl + dl, nh = kh + dh, nw = rx + dw;
    bool valid = act && (nl >= 0) && (nl < KL) && (nh >= 0) && (nh < KH)
                     && (nw >= 0) && (nw < KW);
    int nlc = min(max(nl, 0), KL - 1);
    int nhc = min(max(nh, 0), KH - 1);
    int nwc = min(max(nw, 0), KW - 1);
    int nidx = nlc * (KH * KW) + nhc * KW + nwc;

    float s0 = 0.f, s1 = 0.f, s2 = 0.f, s3 = 0.f, s4 = 0.f, s5 = 0.f;
    if (act) {
        const float* sp = g_spFeat + nidx * 6;
        s0 = __ldg(sp + 0); s1 = __ldg(sp + 1); s2 = __ldg(sp + 2);
        s3 = __ldg(sp + 3); s4 = __ldg(sp + 4); s5 = __ldg(sp + 5);
    }

    float fT = T_SCALE * (float)t;
    float fY = YX_SCALE * (float)y;
    float fX0 = YX_SCALE * (float)x0;
    int base = t * HW + y * WW + x0;

    // per-lane invariants of the distance
    float tT = fT - s0, tY = fY - s1;
    float dYT = tT * tT + tY * tY;
    float tX0 = fX0 - s2;

    const float* lb0 = lab + base;
    const float* lb1 = lab + NN + base;
    const float* lb2 = lab + 2 * NN + base;

    float aw = 0.f, ap = 0.f, a3 = 0.f, a4 = 0.f, a5 = 0.f;

    #pragma unroll
    for (int p = 0; p < RUNW; p++) {
        float r0 = __ldg(lb0 + p);
        float r1 = __ldg(lb1 + p);
        float r2 = __ldg(lb2 + p);
        float tX = fmaf((float)p, YX_SCALE, tX0);
        float l0 = fmaf(LAB_SCALE, r0, -s3);
        float l1 = fmaf(LAB_SCALE, r1, -s4);
        float l2 = fmaf(LAB_SCALE, r2, -s5);
        float d = fmaf(tX, tX, dYT);
        d = fmaf(l0, l0, d);
        d = fmaf(l1, l1, d);
        d = fmaf(l2, l2, d);

        // min(d) over valid lanes (d >= 0 -> uint order == float order)
        unsigned dbits = valid ? __float_as_uint(d) : 0x7F800000u;
        unsigned dmin  = __reduce_min_sync(FULLMASK, dbits);
        float e = valid ? __expf(__uint_as_float(dmin) - d) : 0.0f;
        // fixed-point sum: e in (0,1], max lane contributes exactly 2^25
        unsigned ei  = __float2uint_rn(e * FXSCALE);
        unsigned smi = __reduce_add_sync(FULLMASK, ei);
        float sum = (float)smi * FXINV;
        float a = __fdividef(e, sum);

        if (FINAL) {
            if (act) sA[j][w * RUNW + p] = a;
            unsigned b  = valid ? __float_as_uint(a) : 0u;
            unsigned mb = __reduce_max_sync(FULLMASK, b);
            unsigned ball = __ballot_sync(FULLMASK, valid && (b == mb));
            int j0 = __ffs(ball) - 1;
            int nbest = __shfl_sync(FULLMASK, nidx, j0);
            if (j == 0) sF[w * RUNW + p] = (float)nbest;
        } else {
            aw += a;
            ap = fmaf(a, (float)p, ap);
            a3 = fmaf(a, r0, a3);
            a4 = fmaf(a, r1, a4);
            a5 = fmaf(a, r2, a5);
        }
    }

    if (!FINAL) {
        if (valid) {
            int rep = blockIdx.x & (RREP - 1);
            float v2 = fmaf(YX_SCALE, ap, fX0 * aw);
            atomicAdd((float4*)&g_acc[rep][nidx][0],
                      make_float4(fT * aw, fY * aw, v2, LAB_SCALE * a3));
            atomicAdd((float4*)&g_acc[rep][nidx][4],
                      make_float4(LAB_SCALE * a4, LAB_SCALE * a5, aw, 0.f));
        }
    } else {
        __syncthreads();
        // block covers 112 consecutive x pixels of one (t,y) row
        int rx0   = (blockIdx.x & 3) * 8;
        int xbase = t * HW + y * WW + rx0 * RUNW;
        #pragma unroll 4
        for (int i = threadIdx.x; i < 27 * 112; i += 256) {
            int jj = i / 112;
            int c  = i - jj * 112;
            outAssoc[jj * NN + xbase + c] = sA[jj][c];
        }
        if (threadIdx.x < 112)
            outFinal[xbase + threadIdx.x] = sF[threadIdx.x];
    }
}

// ---------------- launch ----------------
extern "C" void kernel_launch(void* const* d_in, const int* in_sizes, int n_in,
                              void* d_out, int out_size) {
    const float* lab = (const float*)d_in[0];   // vid_lab (1,3,L,H,W)
    // d_in[1] = init_spIndx (regular grid; recomputed analytically in-kernel)

    float* out = (float*)d_out;
    float* outPFeat = out;                               // 6*N
    float* outSp    = out + 6 * NN;                      // 6*K
    float* outAssoc = out + 6 * NN + 6 * KK;             // 27*N
    float* outFinal = out + 6 * NN + 6 * KK + 27 * NN;   // N

    const int EM_BLOCKS = NRUNS / 8;   // 8 warps (runs) per 256-thread block

    zero_acc_kernel<<<(RREP * KK * 8 + 255) / 256, 256>>>();
    init_kernel<<<EM_BLOCKS, 256>>>(lab, outPFeat);
    norm_kernel<0><<<(KK + 127) / 128, 128>>>(nullptr);

    for (int it = 0; it < 4; it++) {
        em_kernel<false><<<EM_BLOCKS, 256>>>(lab, nullptr, nullptr);
        norm_kernel<1><<<(KK + 127) / 128, 128>>>(it == 3 ? outSp : nullptr);
    }
    em_kernel<true><<<EM_BLOCKS, 256>>>(lab, outAssoc, outFinal);
}

// round 5
// speedup vs baseline: 3.1587x; 1.1032x over previous
#include <cuda_runtime.h>

// ---------------- problem constants ----------------
#define LL 8
#define HH 256
#define WW 448
#define KL 2
#define KH 18
#define KW 32
#define KK (KL*KH*KW)        // 1152 superpixels
#define HW (HH*WW)           // 114688
#define NN (LL*HW)           // 917504 pixels
#define RUNW 14              // W / KW = exact pixels per kw cell
#define NRUNS (NN/RUNW)      // 65536 runs (one warp each)
#define RREP 4               // accumulator replicas (contention relief)

#define T_SCALE   0.625f                 // Kl/(0.4*L)
#define YX_SCALE  0.17857142857142858f   // max(Kh/(0.4*H), Kw/(0.4*W))
#define LAB_SCALE 0.26f

#define FXSCALE   33554432.0f            // 2^25 fixed-point softmax denominator
#define FXINV     (1.0f/33554432.0f)

#define FULLMASK 0xFFFFFFFFu

typedef unsigned long long ull;

// ---------------- packed f32x2 helpers (PTX-only on Blackwell) ----------------
__device__ __forceinline__ ull pk2(float lo, float hi) {
    ull r; asm("mov.b64 %0, {%1, %2};" : "=l"(r) : "f"(lo), "f"(hi)); return r;
}
__device__ __forceinline__ void upk2(ull v, float& lo, float& hi) {
    asm("mov.b64 {%0, %1}, %2;" : "=f"(lo), "=f"(hi) : "l"(v));
}
__device__ __forceinline__ ull fma2(ull a, ull b, ull c) {
    ull r; asm("fma.rn.f32x2 %0, %1, %2, %3;" : "=l"(r) : "l"(a), "l"(b), "l"(c)); return r;
}
__device__ __forceinline__ ull add2(ull a, ull b) {
    ull r; asm("add.rn.f32x2 %0, %1, %2;" : "=l"(r) : "l"(a), "l"(b)); return r;
}

// ---------------- persistent scratch (no allocs allowed) ----------------
__device__ float g_spFeat[KK * 6];                       // cluster features
__device__ __align__(32) float g_acc[RREP][KK][8];       // [0..5]=sum a*f, [6]=sum a, [7]=pad

// ---------------- kernels ----------------
__global__ void zero_acc_kernel() {
    int i = blockIdx.x * blockDim.x + threadIdx.x;
    if (i < RREP * KK * 8) ((float*)g_acc)[i] = 0.0f;
}

// Writes pFeat5 output and accumulates the scatter-mean init (per-run warp reduce).
__global__ void init_kernel(const float* __restrict__ lab,
                            float* __restrict__ outPFeat) {
    int gw   = (blockIdx.x * blockDim.x + threadIdx.x) >> 5;
    int lane = threadIdx.x & 31;
    int rx  = gw & (KW - 1);
    int row = gw >> 5;
    int y = row & (HH - 1);
    int t = row >> 8;
    int x0 = rx * RUNW;
    int kl = t >> 2;
    int kh = (y * KH) >> 8;
    int c0 = kl * (KH * KW) + kh * KW + rx;

    float f0 = 0.f, f1 = 0.f, f2 = 0.f, f3 = 0.f, f4 = 0.f, f5 = 0.f;
    if (lane < RUNW) {
        int x = x0 + lane;
        int pix = t * HW + y * WW + x;
        f0 = T_SCALE * (float)t;
        f1 = YX_SCALE * (float)y;
        f2 = YX_SCALE * (float)x;
        f3 = LAB_SCALE * __ldg(lab + pix);
        f4 = LAB_SCALE * __ldg(lab + NN + pix);
        f5 = LAB_SCALE * __ldg(lab + 2 * NN + pix);
        outPFeat[pix]          = f0;
        outPFeat[NN + pix]     = f1;
        outPFeat[2 * NN + pix] = f2;
        outPFeat[3 * NN + pix] = f3;
        outPFeat[4 * NN + pix] = f4;
        outPFeat[5 * NN + pix] = f5;
    }
    float s0 = f0, s1 = f1, s2 = f2, s3 = f3, s4 = f4, s5 = f5;
    #pragma unroll
    for (int o = 16; o; o >>= 1) {
        s0 += __shfl_xor_sync(FULLMASK, s0, o);
        s1 += __shfl_xor_sync(FULLMASK, s1, o);
        s2 += __shfl_xor_sync(FULLMASK, s2, o);
        s3 += __shfl_xor_sync(FULLMASK, s3, o);
        s4 += __shfl_xor_sync(FULLMASK, s4, o);
        s5 += __shfl_xor_sync(FULLMASK, s5, o);
    }
    if (lane == 0) {
        int rep = blockIdx.x & (RREP - 1);
        atomicAdd((float4*)&g_acc[rep][c0][0], make_float4(s0, s1, s2, s3));
        atomicAdd((float4*)&g_acc[rep][c0][4], make_float4(s4, s5, (float)RUNW, 0.f));
    }
}

// MODE 0: init normalize; MODE 1: EM update. Folds RREP replicas, zeros them.
template <int MODE>
__global__ void norm_kernel(float* __restrict__ spOut) {
    int k = blockIdx.x * blockDim.x + threadIdx.x;
    if (k >= KK) return;
    float acc[7];
    #pragma unroll
    for (int c = 0; c < 7; c++) acc[c] = 0.0f;
    #pragma unroll
    for (int r = 0; r < RREP; r++) {
        #pragma unroll
        for (int c = 0; c < 7; c++) {
            acc[c] += g_acc[r][k][c];
            g_acc[r][k][c] = 0.0f;
        }
    }
    float w = acc[6];
    float denom = (MODE == 0) ? fmaxf(w, 1.0f) : fmaxf(w, 1e-12f);
    float inv = 1.0f / denom;
    #pragma unroll
    for (int c = 0; c < 6; c++) {
        float v = acc[c] * inv;
        g_spFeat[k * 6 + c] = v;
        if (spOut) spOut[c * KK + k] = v;
    }
}

// One EM pass. Warp = one 14-pixel run; lane j<27 = neighbor j.
// Pixels processed in PAIRS with packed f32x2 math for the distance chain
// and the accumulators. Softmax: REDUX min(d) -> exp -> fixed-point REDUX add.
template <bool FINAL>
__global__ void __launch_bounds__(256)
em_kernel(const float* __restrict__ lab,
          float* __restrict__ outAssoc,
          float* __restrict__ outFinal) {
    __shared__ float sA[FINAL ? 27 : 1][FINAL ? 113 : 1];
    __shared__ float sF[FINAL ? 112 : 1];

    int w  = threadIdx.x >> 5;
    int j  = threadIdx.x & 31;
    int gw = blockIdx.x * 8 + w;
    int rx  = gw & (KW - 1);
    int row = gw >> 5;
    int y = row & (HH - 1);
    int t = row >> 8;
    int x0 = rx * RUNW;
    int kl = t >> 2;
    int kh = (y * KH) >> 8;

    bool act = (j < 27);
    int dl = j / 9 - 1;
    int dh = (j % 9) / 3 - 1;
    int dw = j % 3 - 1;
    int nl = kl + dl, nh = kh + dh, nw = rx + dw;
    bool valid = act && (nl >= 0) && (nl < KL) && (nh >= 0) && (nh < KH)
                     && (nw >= 0) && (nw < KW);
    int nlc = min(max(nl, 0), KL - 1);
    int nhc = min(max(nh, 0), KH - 1);
    int nwc = min(max(nw, 0), KW - 1);
    int nidx = nlc * (KH * KW) + nhc * KW + nwc;

    float s0 = 0.f, s1 = 0.f, s2 = 0.f, s3 = 0.f, s4 = 0.f, s5 = 0.f;
    if (act) {
        const float* sp = g_spFeat + nidx * 6;
        s0 = __ldg(sp + 0); s1 = __ldg(sp + 1); s2 = __ldg(sp + 2);
        s3 = __ldg(sp + 3); s4 = __ldg(sp + 4); s5 = __ldg(sp + 5);
    }

    float fT = T_SCALE * (float)t;
    float fY = YX_SCALE * (float)y;
    float fX0 = YX_SCALE * (float)x0;
    int base = t * HW + y * WW + x0;   // even -> float2 loads are 8B aligned

    // per-lane invariants
    float tT = fT - s0, tY = fY - s1;
    float dYT = tT * tT + tY * tY;
    float tX0 = fX0 - s2;

    // packed per-lane constants
    ull dYT2 = pk2(dYT, dYT);
    ull tX02 = pk2(tX0, tX0);
    ull LAB2 = pk2(LAB_SCALE, LAB_SCALE);
    ull ns3  = pk2(-s3, -s3);
    ull ns4  = pk2(-s4, -s4);
    ull ns5  = pk2(-s5, -s5);

    const float* lb0 = lab + base;
    const float* lb1 = lab + NN + base;
    const float* lb2 = lab + 2 * NN + base;

    ull aw2 = 0, ap2 = 0, a32 = 0, a42 = 0, a52 = 0;

    #pragma unroll
    for (int p = 0; p < RUNW; p += 2) {
        float2 v0 = __ldg((const float2*)(lb0 + p));
        float2 v1 = __ldg((const float2*)(lb1 + p));
        float2 v2 = __ldg((const float2*)(lb2 + p));
        ull r0 = pk2(v0.x, v0.y);
        ull r1 = pk2(v1.x, v1.y);
        ull r2 = pk2(v2.x, v2.y);

        // tX pair = tX0 + (p, p+1)*YX  (compile-time constant pair)
        ull ofs = pk2((float)p * YX_SCALE, (float)(p + 1) * YX_SCALE);
        ull tX2 = add2(tX02, ofs);
        ull l02 = fma2(LAB2, r0, ns3);
        ull l12 = fma2(LAB2, r1, ns4);
        ull l22 = fma2(LAB2, r2, ns5);
        ull d2  = fma2(tX2, tX2, dYT2);
        d2 = fma2(l02, l02, d2);
        d2 = fma2(l12, l12, d2);
        d2 = fma2(l22, l22, d2);

        float dA, dB;
        upk2(d2, dA, dB);

        // ---- pixel p ----
        unsigned dbA = valid ? __float_as_uint(dA) : 0x7F800000u;
        unsigned dmA = __reduce_min_sync(FULLMASK, dbA);
        float eA = valid ? __expf(__uint_as_float(dmA) - dA) : 0.0f;
        unsigned smA = __reduce_add_sync(FULLMASK, __float2uint_rn(eA * FXSCALE));
        float aA = __fdividef(eA, (float)smA * FXINV);

        // ---- pixel p+1 ----
        unsigned dbB = valid ? __float_as_uint(dB) : 0x7F800000u;
        unsigned dmB = __reduce_min_sync(FULLMASK, dbB);
        float eB = valid ? __expf(__uint_as_float(dmB) - dB) : 0.0f;
        unsigned smB = __reduce_add_sync(FULLMASK, __float2uint_rn(eB * FXSCALE));
        float aB = __fdividef(eB, (float)smB * FXINV);

        if (FINAL) {
            if (act) {
                sA[j][w * RUNW + p]     = aA;
                sA[j][w * RUNW + p + 1] = aB;
            }
            unsigned bA = valid ? __float_as_uint(aA) : 0u;
            unsigned mA = __reduce_max_sync(FULLMASK, bA);
            unsigned ballA = __ballot_sync(FULLMASK, valid && (bA == mA));
            int nbA = __shfl_sync(FULLMASK, nidx, __ffs(ballA) - 1);
            unsigned bB = valid ? __float_as_uint(aB) : 0u;
            unsigned mB = __reduce_max_sync(FULLMASK, bB);
            unsigned ballB = __ballot_sync(FULLMASK, valid && (bB == mB));
            int nbB = __shfl_sync(FULLMASK, nidx, __ffs(ballB) - 1);
            if (j == 0) {
                sF[w * RUNW + p]     = (float)nbA;
                sF[w * RUNW + p + 1] = (float)nbB;
            }
        } else {
            ull a2 = pk2(aA, aB);
            aw2 = add2(aw2, a2);
            ull pc = pk2((float)p, (float)(p + 1));
            ap2 = fma2(a2, pc, ap2);
            a32 = fma2(a2, r0, a32);
            a42 = fma2(a2, r1, a42);
            a52 = fma2(a2, r2, a52);
        }
    }

    if (!FINAL) {
        if (valid) {
            float awA, awB, apA, apB, x3A, x3B, x4A, x4B, x5A, x5B;
            upk2(aw2, awA, awB); upk2(ap2, apA, apB);
            upk2(a32, x3A, x3B); upk2(a42, x4A, x4B); upk2(a52, x5A, x5B);
            float aw = awA + awB;
            float ap = apA + apB;
            float a3 = x3A + x3B, a4 = x4A + x4B, a5 = x5A + x5B;
            int rep = blockIdx.x & (RREP - 1);
            float v2 = fmaf(YX_SCALE, ap, fX0 * aw);
            atomicAdd((float4*)&g_acc[rep][nidx][0],
                      make_float4(fT * aw, fY * aw, v2, LAB_SCALE * a3));
            atomicAdd((float4*)&g_acc[rep][nidx][4],
                      make_float4(LAB_SCALE * a4, LAB_SCALE * a5, aw, 0.f));
        }
    } else {
        __syncthreads();
        // block covers 112 consecutive x pixels of one (t,y) row
        int rx0   = (blockIdx.x & 3) * 8;
        int xbase = t * HW + y * WW + rx0 * RUNW;
        #pragma unroll 4
        for (int i = threadIdx.x; i < 27 * 112; i += 256) {
            int jj = i / 112;
            int c  = i - jj * 112;
            outAssoc[jj * NN + xbase + c] = sA[jj][c];
        }
        if (threadIdx.x < 112)
            outFinal[xbase + threadIdx.x] = sF[threadIdx.x];
    }
}

// ---------------- launch ----------------
extern "C" void kernel_launch(void* const* d_in, const int* in_sizes, int n_in,
                              void* d_out, int out_size) {
    const float* lab = (const float*)d_in[0];   // vid_lab (1,3,L,H,W)
    // d_in[1] = init_spIndx (regular grid; recomputed analytically in-kernel)

    float* out = (float*)d_out;
    float* outPFeat = out;                               // 6*N
    float* outSp    = out + 6 * NN;                      // 6*K
    float* outAssoc = out + 6 * NN + 6 * KK;             // 27*N
    float* outFinal = out + 6 * NN + 6 * KK + 27 * NN;   // N

    const int EM_BLOCKS = NRUNS / 8;   // 8 warps (runs) per 256-thread block

    zero_acc_kernel<<<(RREP * KK * 8 + 255) / 256, 256>>>();
    init_kernel<<<EM_BLOCKS, 256>>>(lab, outPFeat);
    norm_kernel<0><<<(KK + 127) / 128, 128>>>(nullptr);

    for (int it = 0; it < 4; it++) {
        em_kernel<false><<<EM_BLOCKS, 256>>>(lab, nullptr, nullptr);
        norm_kernel<1><<<(KK + 127) / 128, 128>>>(it == 3 ? outSp : nullptr);
    }
    em_kernel<true><<<EM_BLOCKS, 256>>>(lab, outAssoc, outFinal);
}

// round 6
// speedup vs baseline: 3.7213x; 1.1781x over previous
#include <cuda_runtime.h>

// ---------------- problem constants ----------------
#define LL 8
#define HH 256
#define WW 448
#define KL 2
#define KH 18
#define KW 32
#define KK (KL*KH*KW)        // 1152 superpixels
#define HW (HH*WW)           // 114688
#define NN (LL*HW)           // 917504 pixels
#define RUNW 14              // W / KW = exact pixels per kw cell
#define NRUNS (NN/RUNW)      // 65536 runs (one warp each)
#define RREP 4               // accumulator replicas (contention relief)

#define T_SCALE   0.625f                 // Kl/(0.4*L)
#define YX_SCALE  0.17857142857142858f   // max(Kh/(0.4*H), Kw/(0.4*W))
#define LAB_SCALE 0.26f
#define L2E       1.4426950408889634f

#define FULLMASK 0xFFFFFFFFu

typedef unsigned long long ull;

// ---------------- packed f32x2 helpers (PTX-only on Blackwell) ----------------
__device__ __forceinline__ ull pk2(float lo, float hi) {
    ull r; asm("mov.b64 %0, {%1, %2};" : "=l"(r) : "f"(lo), "f"(hi)); return r;
}
__device__ __forceinline__ void upk2(ull v, float& lo, float& hi) {
    asm("mov.b64 {%0, %1}, %2;" : "=f"(lo), "=f"(hi) : "l"(v));
}
__device__ __forceinline__ ull fma2(ull a, ull b, ull c) {
    ull r; asm("fma.rn.f32x2 %0, %1, %2, %3;" : "=l"(r) : "l"(a), "l"(b), "l"(c)); return r;
}
__device__ __forceinline__ ull add2(ull a, ull b) {
    ull r; asm("add.rn.f32x2 %0, %1, %2;" : "=l"(r) : "l"(a), "l"(b)); return r;
}
// 2^x approx (same HW unit __expf uses)
__device__ __forceinline__ float ex2f(float x) {
    float r; asm("ex2.approx.ftz.f32 %0, %1;" : "=f"(r) : "f"(x)); return r;
}

// ---------------- persistent scratch (no allocs allowed) ----------------
// Invariant: g_acc is all-zero at kernel_launch entry (zero-initialized at
// module load; every norm_kernel re-zeroes exactly what was accumulated).
__device__ float g_spFeat[KK * 6];                       // cluster features
__device__ __align__(32) float g_acc[RREP][KK][8];       // [0..5]=sum a*f, [6]=sum a, [7]=pad

// ---------------- kernels ----------------
// Writes pFeat5 output and accumulates the scatter-mean init (per-run warp reduce).
__global__ void init_kernel(const float* __restrict__ lab,
                            float* __restrict__ outPFeat) {
    int gw   = (blockIdx.x * blockDim.x + threadIdx.x) >> 5;
    int lane = threadIdx.x & 31;
    int rx  = gw & (KW - 1);
    int row = gw >> 5;
    int y = row & (HH - 1);
    int t = row >> 8;
    int x0 = rx * RUNW;
    int kl = t >> 2;
    int kh = (y * KH) >> 8;
    int c0 = kl * (KH * KW) + kh * KW + rx;

    float f0 = 0.f, f1 = 0.f, f2 = 0.f, f3 = 0.f, f4 = 0.f, f5 = 0.f;
    if (lane < RUNW) {
        int x = x0 + lane;
        int pix = t * HW + y * WW + x;
        f0 = T_SCALE * (float)t;
        f1 = YX_SCALE * (float)y;
        f2 = YX_SCALE * (float)x;
        f3 = LAB_SCALE * __ldg(lab + pix);
        f4 = LAB_SCALE * __ldg(lab + NN + pix);
        f5 = LAB_SCALE * __ldg(lab + 2 * NN + pix);
        outPFeat[pix]          = f0;
        outPFeat[NN + pix]     = f1;
        outPFeat[2 * NN + pix] = f2;
        outPFeat[3 * NN + pix] = f3;
        outPFeat[4 * NN + pix] = f4;
        outPFeat[5 * NN + pix] = f5;
    }
    float s0 = f0, s1 = f1, s2 = f2, s3 = f3, s4 = f4, s5 = f5;
    #pragma unroll
    for (int o = 16; o; o >>= 1) {
        s0 += __shfl_xor_sync(FULLMASK, s0, o);
        s1 += __shfl_xor_sync(FULLMASK, s1, o);
        s2 += __shfl_xor_sync(FULLMASK, s2, o);
        s3 += __shfl_xor_sync(FULLMASK, s3, o);
        s4 += __shfl_xor_sync(FULLMASK, s4, o);
        s5 += __shfl_xor_sync(FULLMASK, s5, o);
    }
    if (lane == 0) {
        int rep = blockIdx.x & (RREP - 1);
        atomicAdd((float4*)&g_acc[rep][c0][0], make_float4(s0, s1, s2, s3));
        atomicAdd((float4*)&g_acc[rep][c0][4], make_float4(s4, s5, (float)RUNW, 0.f));
    }
}

// MODE 0: init normalize; MODE 1: EM update. Folds RREP replicas, zeros them.
template <int MODE>
__global__ void norm_kernel(float* __restrict__ spOut) {
    int k = blockIdx.x * blockDim.x + threadIdx.x;
    if (k >= KK) return;
    float acc[7];
    #pragma unroll
    for (int c = 0; c < 7; c++) acc[c] = 0.0f;
    #pragma unroll
    for (int r = 0; r < RREP; r++) {
        #pragma unroll
        for (int c = 0; c < 7; c++) {
            acc[c] += g_acc[r][k][c];
            g_acc[r][k][c] = 0.0f;
        }
    }
    float w = acc[6];
    float denom = (MODE == 0) ? fmaxf(w, 1.0f) : fmaxf(w, 1e-12f);
    float inv = 1.0f / denom;
    #pragma unroll
    for (int c = 0; c < 6; c++) {
        float v = acc[c] * inv;
        g_spFeat[k * 6 + c] = v;
        if (spOut) spOut[c * KK + k] = v;
    }
}

// One EM pass. Warp = one 14-pixel run; lane j<27 = neighbor j.
// Pixel pairs in packed f32x2. Softmax: e_scaled = 2^(25 - d*log2e) in [0,2^25],
// summed with one fixed-point REDUX.add (no max-subtraction: d>=0 and d_min is
// always small, so quantization keeps >=13 significant bits).
template <bool FINAL>
__global__ void __launch_bounds__(256, 6)
em_kernel(const float* __restrict__ lab,
          float* __restrict__ outAssoc,
          float* __restrict__ outFinal) {
    __shared__ float sA[FINAL ? 27 : 1][FINAL ? 113 : 1];
    __shared__ float sF[FINAL ? 112 : 1];

    int w  = threadIdx.x >> 5;
    int j  = threadIdx.x & 31;
    int gw = blockIdx.x * 8 + w;
    int rx  = gw & (KW - 1);
    int row = gw >> 5;
    int y = row & (HH - 1);
    int t = row >> 8;
    int x0 = rx * RUNW;
    int kl = t >> 2;
    int kh = (y * KH) >> 8;

    bool act = (j < 27);
    int dl = j / 9 - 1;
    int dh = (j % 9) / 3 - 1;
    int dw = j % 3 - 1;
    int nl = kl + dl, nh = kh + dh, nw = rx + dw;
    bool valid = act && (nl >= 0) && (nl < KL) && (nh >= 0) && (nh < KH)
                     && (nw >= 0) && (nw < KW);
    int nlc = min(max(nl, 0), KL - 1);
    int nhc = min(max(nh, 0), KH - 1);
    int nwc = min(max(nw, 0), KW - 1);
    int nidx = nlc * (KH * KW) + nhc * KW + nwc;

    float s0 = 0.f, s1 = 0.f, s2 = 0.f, s3 = 0.f, s4 = 0.f, s5 = 0.f;
    if (act) {
        const float* sp = g_spFeat + nidx * 6;
        s0 = __ldg(sp + 0); s1 = __ldg(sp + 1); s2 = __ldg(sp + 2);
        s3 = __ldg(sp + 3); s4 = __ldg(sp + 4); s5 = __ldg(sp + 5);
    }

    float fT = T_SCALE * (float)t;
    float fY = YX_SCALE * (float)y;
    float fX0 = YX_SCALE * (float)x0;
    int base = t * HW + y * WW + x0;   // even -> 8B-aligned pair loads

    // per-lane invariants
    float tT = fT - s0, tY = fY - s1;
    float dYT = tT * tT + tY * tY;
    float tX0 = fX0 - s2;

    // packed per-lane constants / running pairs
    ull dYT2  = pk2(dYT, dYT);
    ull tX2   = pk2(tX0, tX0 + YX_SCALE);
    ull stepX = pk2(2.0f * YX_SCALE, 2.0f * YX_SCALE);
    ull LAB2  = pk2(LAB_SCALE, LAB_SCALE);
    ull ns3   = pk2(-s3, -s3);
    ull ns4   = pk2(-s4, -s4);
    ull ns5   = pk2(-s5, -s5);

    const float* lb0 = lab + base;
    const float* lb1 = lab + NN + base;
    const float* lb2 = lab + 2 * NN + base;

    ull aw2 = 0, ap2 = 0, a32 = 0, a42 = 0, a52 = 0;
    ull pc2 = pk2(0.0f, 1.0f);
    ull two2 = pk2(2.0f, 2.0f);

    #pragma unroll
    for (int p = 0; p < RUNW; p += 2) {
        ull r0 = __ldg((const ull*)(lb0 + p));
        ull r1 = __ldg((const ull*)(lb1 + p));
        ull r2 = __ldg((const ull*)(lb2 + p));

        ull l02 = fma2(LAB2, r0, ns3);
        ull l12 = fma2(LAB2, r1, ns4);
        ull l22 = fma2(LAB2, r2, ns5);
        ull d2  = fma2(tX2, tX2, dYT2);
        d2 = fma2(l02, l02, d2);
        d2 = fma2(l12, l12, d2);
        d2 = fma2(l22, l22, d2);
        tX2 = add2(tX2, stepX);

        float dA, dB;
        upk2(d2, dA, dB);

        // ---- pixel p: e_scaled = 2^(25 - d*log2e) ----
        float esA = valid ? ex2f(fmaf(dA, -L2E, 25.0f)) : 0.0f;
        unsigned smA = __reduce_add_sync(FULLMASK, __float2uint_rn(esA));
        float aA = __fdividef(esA, (float)smA);

        // ---- pixel p+1 ----
        float esB = valid ? ex2f(fmaf(dB, -L2E, 25.0f)) : 0.0f;
        unsigned smB = __reduce_add_sync(FULLMASK, __float2uint_rn(esB));
        float aB = __fdividef(esB, (float)smB);

        if (FINAL) {
            if (act) {
                sA[j][w * RUNW + p]     = aA;
                sA[j][w * RUNW + p + 1] = aB;
            }
            unsigned bA = valid ? __float_as_uint(aA) : 0u;
            unsigned mA = __reduce_max_sync(FULLMASK, bA);
            unsigned ballA = __ballot_sync(FULLMASK, valid && (bA == mA));
            int nbA = __shfl_sync(FULLMASK, nidx, __ffs(ballA) - 1);
            unsigned bB = valid ? __float_as_uint(aB) : 0u;
            unsigned mB = __reduce_max_sync(FULLMASK, bB);
            unsigned ballB = __ballot_sync(FULLMASK, valid && (bB == mB));
            int nbB = __shfl_sync(FULLMASK, nidx, __ffs(ballB) - 1);
            if (j == 0) {
                sF[w * RUNW + p]     = (float)nbA;
                sF[w * RUNW + p + 1] = (float)nbB;
            }
        } else {
            ull a2 = pk2(aA, aB);
            aw2 = add2(aw2, a2);
            ap2 = fma2(a2, pc2, ap2);
            pc2 = add2(pc2, two2);
            a32 = fma2(a2, r0, a32);
            a42 = fma2(a2, r1, a42);
            a52 = fma2(a2, r2, a52);
        }
    }

    if (!FINAL) {
        if (valid) {
            float awA, awB, apA, apB, x3A, x3B, x4A, x4B, x5A, x5B;
            upk2(aw2, awA, awB); upk2(ap2, apA, apB);
            upk2(a32, x3A, x3B); upk2(a42, x4A, x4B); upk2(a52, x5A, x5B);
            float aw = awA + awB;
            float ap = apA + apB;
            float a3 = x3A + x3B, a4 = x4A + x4B, a5 = x5A + x5B;
            int rep = blockIdx.x & (RREP - 1);
            float v2 = fmaf(YX_SCALE, ap, fX0 * aw);
            atomicAdd((float4*)&g_acc[rep][nidx][0],
                      make_float4(fT * aw, fY * aw, v2, LAB_SCALE * a3));
            atomicAdd((float4*)&g_acc[rep][nidx][4],
                      make_float4(LAB_SCALE * a4, LAB_SCALE * a5, aw, 0.f));
        }
    } else {
        __syncthreads();
        // block covers 112 consecutive x pixels of one (t,y) row
        int rx0   = (blockIdx.x & 3) * 8;
        int xbase = t * HW + y * WW + rx0 * RUNW;
        #pragma unroll 4
        for (int i = threadIdx.x; i < 27 * 112; i += 256) {
            int jj = i / 112;
            int c  = i - jj * 112;
            outAssoc[jj * NN + xbase + c] = sA[jj][c];
        }
        if (threadIdx.x < 112)
            outFinal[xbase + threadIdx.x] = sF[threadIdx.x];
    }
}

// ---------------- launch ----------------
extern "C" void kernel_launch(void* const* d_in, const int* in_sizes, int n_in,
                              void* d_out, int out_size) {
    const float* lab = (const float*)d_in[0];   // vid_lab (1,3,L,H,W)
    // d_in[1] = init_spIndx (regular grid; recomputed analytically in-kernel)

    float* out = (float*)d_out;
    float* outPFeat = out;                               // 6*N
    float* outSp    = out + 6 * NN;                      // 6*K
    float* outAssoc = out + 6 * NN + 6 * KK;             // 27*N
    float* outFinal = out + 6 * NN + 6 * KK + 27 * NN;   // N

    const int EM_BLOCKS = NRUNS / 8;   // 8 warps (runs) per 256-thread block

    init_kernel<<<EM_BLOCKS, 256>>>(lab, outPFeat);
    norm_kernel<0><<<(KK + 127) / 128, 128>>>(nullptr);

    for (int it = 0; it < 4; it++) {
        em_kernel<false><<<EM_BLOCKS, 256>>>(lab, nullptr, nullptr);
        norm_kernel<1><<<(KK + 127) / 128, 128>>>(it == 3 ? outSp : nullptr);
    }
    em_kernel<true><<<EM_BLOCKS, 256>>>(lab, outAssoc, outFinal);
}